// round 9
// baseline (speedup 1.0000x reference)
#include <cuda_runtime.h>

#define N_NODES 50000
#define K_DIM 32
#define F_DIM 128
#define NEG_SLOPE 0.01f
#define WARPS_PER_BLOCK 4
#define KBATCH 8
#define GRID_BLOCKS (148 * 16)

__global__ __launch_bounds__(WARPS_PER_BLOCK * 32)
void gat_symmetry_reduce_kernel(
    const float* __restrict__ a1_node,   // (N,1)
    const float* __restrict__ a2_node,   // (N,1)
    const float* __restrict__ a1_mail,   // (N,K,1)
    const float* __restrict__ a2_mail,   // (N,K,1)
    const float* __restrict__ ft,        // (N,K,F)
    float* __restrict__ out)             // (N,F)
{
    const int warp = threadIdx.x >> 5;
    const int lane = threadIdx.x & 31;
    const int stride = gridDim.x * WARPS_PER_BLOCK;

    int n = blockIdx.x * WARPS_PER_BLOCK + warp;
    // Hoisted, strength-reduced pointers (advance by constant stride per trip).
    const float4* __restrict__ ftp =
        (const float4*)(ft + (size_t)n * (K_DIM * F_DIM)) + lane;
    float4* __restrict__ outp =
        (float4*)(out + (size_t)n * F_DIM) + lane;
    const size_t ft_step  = (size_t)stride * (K_DIM * F_DIM / 4);
    const size_t out_step = (size_t)stride * (F_DIM / 4);

    for (; n < N_NODES; n += stride, ftp += ft_step, outp += out_step) {

        // ---- logits: lane k owns attention slot k (K == 32 == warp size) ----
        const float base = __ldg(&a1_node[n]) + 2.0f * __ldg(&a2_node[n]);
        const float m1 = __ldg(&a1_mail[(size_t)n * K_DIM + lane]);
        const float m2 = __ldg(&a2_mail[(size_t)n * K_DIM + lane]);
        const float x = base + 2.0f * m1 + m2;
        const float logit = (x > 0.0f) ? x : NEG_SLOPE * x;

        // ---- warp softmax over K ----
        float mx = logit;
        #pragma unroll
        for (int o = 16; o > 0; o >>= 1)
            mx = fmaxf(mx, __shfl_xor_sync(0xffffffffu, mx, o));
        const float ex = __expf(logit - mx);
        float s = ex;
        #pragma unroll
        for (int o = 16; o > 0; o >>= 1)
            s += __shfl_xor_sync(0xffffffffu, s, o);
        const float e = ex / s;   // lane k holds e_k

        // ---- weighted sum: lane l owns output cols [4l, 4l+4) ----
        // Streaming (evict-first) loads: ft has zero reuse, keep it out of L2.
        float4 acc = make_float4(0.f, 0.f, 0.f, 0.f);

        #pragma unroll
        for (int kb = 0; kb < K_DIM; kb += KBATCH) {
            float4 v[KBATCH];
            #pragma unroll
            for (int j = 0; j < KBATCH; j++)
                v[j] = __ldcs(ftp + (size_t)(kb + j) * (F_DIM / 4));
            #pragma unroll
            for (int j = 0; j < KBATCH; j++) {
                const float ek = __shfl_sync(0xffffffffu, e, kb + j);
                acc.x = fmaf(ek, v[j].x, acc.x);
                acc.y = fmaf(ek, v[j].y, acc.y);
                acc.z = fmaf(ek, v[j].z, acc.z);
                acc.w = fmaf(ek, v[j].w, acc.w);
            }
        }

        __stcs(outp, acc);
    }
}

extern "C" void kernel_launch(void* const* d_in, const int* in_sizes, int n_in,
                              void* d_out, int out_size) {
    const float* a1_node = (const float*)d_in[0];
    const float* a2_node = (const float*)d_in[1];
    const float* a1_mail = (const float*)d_in[2];
    const float* a2_mail = (const float*)d_in[3];
    const float* ft      = (const float*)d_in[4];
    float* out = (float*)d_out;

    gat_symmetry_reduce_kernel<<<GRID_BLOCKS, WARPS_PER_BLOCK * 32>>>(
        a1_node, a2_node, a1_mail, a2_mail, ft, out);
}

// round 10
// speedup vs baseline: 1.0205x; 1.0205x over previous
#include <cuda_runtime.h>

#define N_NODES 50000
#define K_DIM 32
#define F_DIM 128
#define NEG_SLOPE 0.01f
#define WARPS_PER_BLOCK 4
#define KBATCH 8
#define GRID_BLOCKS (148 * 16)

__global__ __launch_bounds__(WARPS_PER_BLOCK * 32)
void gat_symmetry_reduce_kernel(
    const float* __restrict__ a1_node,   // (N,1)
    const float* __restrict__ a2_node,   // (N,1)
    const float* __restrict__ a1_mail,   // (N,K,1)
    const float* __restrict__ a2_mail,   // (N,K,1)
    const float* __restrict__ ft,        // (N,K,F)
    float* __restrict__ out)             // (N,F)
{
    const int warp = threadIdx.x >> 5;
    const int lane = threadIdx.x & 31;
    const int stride = gridDim.x * WARPS_PER_BLOCK;

    int n = blockIdx.x * WARPS_PER_BLOCK + warp;
    // Hoisted, strength-reduced pointers (advance by constant stride per trip).
    const float4* __restrict__ ftp =
        (const float4*)(ft + (size_t)n * (K_DIM * F_DIM)) + lane;
    float4* __restrict__ outp =
        (float4*)(out + (size_t)n * F_DIM) + lane;
    const size_t ft_step  = (size_t)stride * (K_DIM * F_DIM / 4);
    const size_t out_step = (size_t)stride * (F_DIM / 4);

    for (; n < N_NODES; n += stride, ftp += ft_step, outp += out_step) {

        // ---- logits: lane k owns attention slot k (K == 32 == warp size) ----
        const float base = __ldg(&a1_node[n]) + 2.0f * __ldg(&a2_node[n]);
        const float m1 = __ldg(&a1_mail[(size_t)n * K_DIM + lane]);
        const float m2 = __ldg(&a2_mail[(size_t)n * K_DIM + lane]);
        const float x = base + 2.0f * m1 + m2;
        const float logit = (x > 0.0f) ? x : NEG_SLOPE * x;

        // ---- warp softmax over K ----
        float mx = logit;
        #pragma unroll
        for (int o = 16; o > 0; o >>= 1)
            mx = fmaxf(mx, __shfl_xor_sync(0xffffffffu, mx, o));
        const float ex = __expf(logit - mx);
        float s = ex;
        #pragma unroll
        for (int o = 16; o > 0; o >>= 1)
            s += __shfl_xor_sync(0xffffffffu, s, o);
        const float e = ex / s;   // lane k holds e_k

        // ---- weighted sum: lane l owns output cols [4l, 4l+4) ----
        // Streaming (evict-first) loads: ft has zero reuse, keep it out of L2.
        float4 acc = make_float4(0.f, 0.f, 0.f, 0.f);

        #pragma unroll
        for (int kb = 0; kb < K_DIM; kb += KBATCH) {
            float4 v[KBATCH];
            #pragma unroll
            for (int j = 0; j < KBATCH; j++)
                v[j] = __ldcs(ftp + (size_t)(kb + j) * (F_DIM / 4));
            #pragma unroll
            for (int j = 0; j < KBATCH; j++) {
                const float ek = __shfl_sync(0xffffffffu, e, kb + j);
                acc.x = fmaf(ek, v[j].x, acc.x);
                acc.y = fmaf(ek, v[j].y, acc.y);
                acc.z = fmaf(ek, v[j].z, acc.z);
                acc.w = fmaf(ek, v[j].w, acc.w);
            }
        }

        __stcs(outp, acc);
    }
}

extern "C" void kernel_launch(void* const* d_in, const int* in_sizes, int n_in,
                              void* d_out, int out_size) {
    const float* a1_node = (const float*)d_in[0];
    const float* a2_node = (const float*)d_in[1];
    const float* a1_mail = (const float*)d_in[2];
    const float* a2_mail = (const float*)d_in[3];
    const float* ft      = (const float*)d_in[4];
    float* out = (float*)d_out;

    gat_symmetry_reduce_kernel<<<GRID_BLOCKS, WARPS_PER_BLOCK * 32>>>(
        a1_node, a2_node, a1_mail, a2_mail, ft, out);
}